// round 15
// baseline (speedup 1.0000x reference)
#include <cuda_runtime.h>
#include <cuda_bf16.h>
#include <math.h>
#include <stdint.h>

// ---------------------------------------------------------------------------
// Problem constants
// ---------------------------------------------------------------------------
#define BATCH   4
#define SEQ     2048
#define DMODEL  2048
#define NHEAD   16
#define HDIM    128
#define BT      (BATCH * SEQ)   // 8192

__device__ __forceinline__ uint32_t smem_to_u32(const void* smem_ptr) {
    uint32_t addr;
    asm("{ .reg .u64 tmp; cvta.to.shared.u64 tmp, %1; cvt.u32.u64 %0, tmp; }"
        : "=r"(addr) : "l"(smem_ptr));
    return addr;
}

#define CP_ASYNC_16(dst_u32, src_ptr) \
    asm volatile("cp.async.cg.shared.global [%0], [%1], 16;" \
        :: "r"(dst_u32), "l"(src_ptr) : "memory")
#define CP_ASYNC_COMMIT() asm volatile("cp.async.commit_group;" ::: "memory")
#define CP_ASYNC_WAIT_1() asm volatile("cp.async.wait_group 1;" ::: "memory")
#define CP_ASYNC_WAIT_0() asm volatile("cp.async.wait_group 0;" ::: "memory")

#define LDMATRIX_X4(r0, r1, r2, r3, addr) \
    asm volatile("ldmatrix.sync.aligned.m8n8.x4.shared.b16 {%0,%1,%2,%3}, [%4];" \
        : "=r"(r0), "=r"(r1), "=r"(r2), "=r"(r3) : "r"(addr))

#define LDMATRIX_X4_TRANS(r0, r1, r2, r3, addr) \
    asm volatile("ldmatrix.sync.aligned.m8n8.x4.trans.shared.b16 {%0,%1,%2,%3}, [%4];" \
        : "=r"(r0), "=r"(r1), "=r"(r2), "=r"(r3) : "r"(addr))

#define MMA_BF16(c, a, b) \
    asm volatile( \
        "mma.sync.aligned.m16n8k16.row.col.f32.bf16.bf16.f32 " \
        "{%0,%1,%2,%3}, {%4,%5,%6,%7}, {%8,%9}, {%0,%1,%2,%3};" \
        : "+f"((c)[0]), "+f"((c)[1]), "+f"((c)[2]), "+f"((c)[3]) \
        : "r"((a)[0]), "r"((a)[1]), "r"((a)[2]), "r"((a)[3]), \
          "r"((b)[0]), "r"((b)[1]))

#define PACK_BF16X2(d, hi_f, lo_f) \
    asm("cvt.rn.bf16x2.f32 %0, %1, %2;" : "=r"(d) : "f"(hi_f), "f"(lo_f))

// ---------------------------------------------------------------------------
// Scratch (allocation-free rule: __device__ globals)
// ---------------------------------------------------------------------------
__device__ float g_q[(size_t)BT * DMODEL];
__device__ float g_k[(size_t)BT * DMODEL];
__device__ float2 g_rope_tab[SEQ * 64];

__device__ __nv_bfloat16 g_xhi[(size_t)BT * DMODEL];
__device__ __nv_bfloat16 g_xlo[(size_t)BT * DMODEL];
__device__ __nv_bfloat16 g_ohi[(size_t)BT * DMODEL];
__device__ __nv_bfloat16 g_olo[(size_t)BT * DMODEL];
__device__ __nv_bfloat16 g_wqhi[(size_t)DMODEL * DMODEL];
__device__ __nv_bfloat16 g_wqlo[(size_t)DMODEL * DMODEL];
__device__ __nv_bfloat16 g_wkhi[(size_t)DMODEL * DMODEL];
__device__ __nv_bfloat16 g_wklo[(size_t)DMODEL * DMODEL];
__device__ __nv_bfloat16 g_wvhi[(size_t)DMODEL * DMODEL];
__device__ __nv_bfloat16 g_wvlo[(size_t)DMODEL * DMODEL];
__device__ __nv_bfloat16 g_wohi[(size_t)DMODEL * DMODEL];
__device__ __nv_bfloat16 g_wolo[(size_t)DMODEL * DMODEL];

__device__ __nv_bfloat16 g_qhi[(size_t)BT * DMODEL];
__device__ __nv_bfloat16 g_qlo[(size_t)BT * DMODEL];
__device__ __nv_bfloat16 g_khi[(size_t)BT * DMODEL];
__device__ __nv_bfloat16 g_klo[(size_t)BT * DMODEL];
__device__ __nv_bfloat16 g_vhi[(size_t)BT * DMODEL];
__device__ __nv_bfloat16 g_vlo[(size_t)BT * DMODEL];

// ---------------------------------------------------------------------------
// Vectorized fp32 -> (bf16 hi, bf16 lo) split: 8 elems/thread
// ---------------------------------------------------------------------------
__device__ __forceinline__
void split8(const float* __restrict__ src,
            __nv_bfloat16* __restrict__ hi, __nv_bfloat16* __restrict__ lo,
            size_t i8) {
    float4 a = *(const float4*)(src + i8);
    float4 b = *(const float4*)(src + i8 + 4);
    float v[8] = {a.x, a.y, a.z, a.w, b.x, b.y, b.z, b.w};
    __nv_bfloat162 ph[4], pl[4];
#pragma unroll
    for (int j = 0; j < 4; j++) {
        __nv_bfloat16 h0 = __float2bfloat16(v[2*j]);
        __nv_bfloat16 h1 = __float2bfloat16(v[2*j+1]);
        ph[j].x = h0; ph[j].y = h1;
        pl[j].x = __float2bfloat16(v[2*j]   - __bfloat162float(h0));
        pl[j].y = __float2bfloat16(v[2*j+1] - __bfloat162float(h1));
    }
    *(uint4*)(hi + i8) = *(uint4*)ph;
    *(uint4*)(lo + i8) = *(uint4*)pl;
}

__global__ __launch_bounds__(256)
void split_bf16_v8(const float* __restrict__ src,
                   __nv_bfloat16* __restrict__ hi, __nv_bfloat16* __restrict__ lo,
                   size_t n) {
    size_t i8 = ((size_t)blockIdx.x * 256 + threadIdx.x) * 8;
    if (i8 >= n) return;
    split8(src, hi, lo, i8);
}

// Fused weight splits: blockIdx.y selects which weight (0=q,1=k,2=v,3=o).
__global__ __launch_bounds__(256)
void split_weights(const float* __restrict__ wq, const float* __restrict__ wk,
                   const float* __restrict__ wv, const float* __restrict__ wo) {
    const size_t nw = (size_t)DMODEL * DMODEL;
    size_t i8 = ((size_t)blockIdx.x * 256 + threadIdx.x) * 8;
    if (i8 >= nw) return;
    switch (blockIdx.y) {
        case 0: split8(wq, g_wqhi, g_wqlo, i8); break;
        case 1: split8(wk, g_wkhi, g_wklo, i8); break;
        case 2: split8(wv, g_wvhi, g_wvlo, i8); break;
        default: split8(wo, g_wohi, g_wolo, i8); break;
    }
}

// ---------------------------------------------------------------------------
// RoPE table in double precision (immune to --use_fast_math)
// ---------------------------------------------------------------------------
__global__ __launch_bounds__(256)
void rope_table_kernel() {
    int idx = blockIdx.x * blockDim.x + threadIdx.x;
    if (idx >= SEQ * 64) return;
    int i = idx & 63;
    int t = idx >> 6;
    float inv_freq = (float)exp(-log(10000.0) * ((double)i / 64.0));
    float ang_f = (float)t * inv_freq;
    double ang = (double)ang_f;
    g_rope_tab[idx] = make_float2((float)cos(ang), (float)sin(ang));
}

// ---------------------------------------------------------------------------
// RoPE + bf16 hi/lo split for q and k (fused)
// ---------------------------------------------------------------------------
__global__ __launch_bounds__(256)
void rope_split_kernel() {
    const size_t total = (size_t)BT * NHEAD * (HDIM / 2);
    size_t idx = (size_t)blockIdx.x * blockDim.x + threadIdx.x;
    if (idx >= total) return;

    int i  = (int)(idx & 63);
    int h  = (int)((idx >> 6) & (NHEAD - 1));
    int bt = (int)(idx >> 10);
    int t  = bt & (SEQ - 1);

    float2 cs = g_rope_tab[t * 64 + i];
    float c = cs.x, s = cs.y;

    size_t base = (size_t)bt * DMODEL + h * HDIM + i;

    float q1 = g_q[base], q2 = g_q[base + 64];
    float qa = q1 * c - q2 * s;
    float qb = q2 * c + q1 * s;
    __nv_bfloat16 qah = __float2bfloat16(qa);
    __nv_bfloat16 qbh = __float2bfloat16(qb);
    g_qhi[base]      = qah; g_qlo[base]      = __float2bfloat16(qa - __bfloat162float(qah));
    g_qhi[base + 64] = qbh; g_qlo[base + 64] = __float2bfloat16(qb - __bfloat162float(qbh));

    float k1 = g_k[base], k2 = g_k[base + 64];
    float ka = k1 * c - k2 * s;
    float kb = k2 * c + k1 * s;
    __nv_bfloat16 kah = __float2bfloat16(ka);
    __nv_bfloat16 kbh = __float2bfloat16(kb);
    g_khi[base]      = kah; g_klo[base]      = __float2bfloat16(ka - __bfloat162float(kah));
    g_khi[base + 64] = kbh; g_klo[base + 64] = __float2bfloat16(kb - __bfloat162float(kbh));
}

// ---------------------------------------------------------------------------
// bf16-split GEMM — 128-thread CTA, 4 warps (2x2), 64x64 warp tile, 2 CTAs/SM.
// 2-stage pipeline with the validated R14 sync ordering.
// R15: B fragments loaded per-nb and immediately consumed (24 MMAs between
// B-loads) — spreads LDSM through the HMMA stream and cuts live registers.
// ---------------------------------------------------------------------------
#define BM 128
#define BN 128
#define BK 32
#define ROWB 80
#define TILE_B (128 * ROWB)
#define STAGE_B (4 * TILE_B)          // 40960 B
#define GEMM_SMEM (2 * STAGE_B)       // 81920 B
#define GTHREADS 128

__device__ __forceinline__
void gemm_body(const __nv_bfloat16* __restrict__ Ahi,
               const __nv_bfloat16* __restrict__ Alo,
               const __nv_bfloat16* __restrict__ Bhi,
               const __nv_bfloat16* __restrict__ Blo,
               float* __restrict__ Cf,
               __nv_bfloat16* __restrict__ Chi,
               __nv_bfloat16* __restrict__ Clo,
               int N, int K, char* smem) {
    const uint32_t sb = smem_to_u32(smem);
    const int tid  = threadIdx.x;
    const int lane = tid & 31;
    const int wid  = tid >> 5;
    const int warp_m = wid & 1;
    const int warp_n = wid >> 1;

    const int row0 = blockIdx.y * BM;
    const int col0 = blockIdx.x * BN;

    float acc[4][8][4];
#pragma unroll
    for (int mi = 0; mi < 4; mi++)
#pragma unroll
        for (int ni = 0; ni < 8; ni++)
#pragma unroll
            for (int e = 0; e < 4; e++) acc[mi][ni][e] = 0.f;

    const int r_ld  = tid >> 2;
    const int c_ld  = (tid & 3) * 16;
    const int ke_ld = (tid & 3) * 8;

    // ---- prologue: stage 0 ----
    {
#pragma unroll
        for (int rnd = 0; rnd < 4; rnd++) {
            int r = r_ld + rnd * 32;
            uint32_t d = sb + r * ROWB + c_ld;
            size_t ga = (size_t)(row0 + r) * K + ke_ld;
            size_t gb = (size_t)(col0 + r) * K + ke_ld;
            CP_ASYNC_16(d + 0 * TILE_B, Ahi + ga);
            CP_ASYNC_16(d + 1 * TILE_B, Alo + ga);
            CP_ASYNC_16(d + 2 * TILE_B, Bhi + gb);
            CP_ASYNC_16(d + 3 * TILE_B, Blo + gb);
        }
        CP_ASYNC_COMMIT();
    }

    const int niter = K / BK;
    for (int kt = 0; kt < niter; kt++) {
        __syncthreads();               // readers of buffer (kt-1)&1 done

        if (kt + 1 < niter) {
            const int k0 = (kt + 1) * BK;
            const uint32_t base = sb + ((kt + 1) & 1) * STAGE_B;
#pragma unroll
            for (int rnd = 0; rnd < 4; rnd++) {
                int r = r_ld + rnd * 32;
                uint32_t d = base + r * ROWB + c_ld;
                size_t ga = (size_t)(row0 + r) * K + k0 + ke_ld;
                size_t gb = (size_t)(col0 + r) * K + k0 + ke_ld;
                CP_ASYNC_16(d + 0 * TILE_B, Ahi + ga);
                CP_ASYNC_16(d + 1 * TILE_B, Alo + ga);
                CP_ASYNC_16(d + 2 * TILE_B, Bhi + gb);
                CP_ASYNC_16(d + 3 * TILE_B, Blo + gb);
            }
        }
        CP_ASYNC_COMMIT();
        CP_ASYNC_WAIT_1();             // own stage-kt group complete
        __syncthreads();               // publish all threads' stage-kt data

        const uint32_t base  = sb + (kt & 1) * STAGE_B;
        const uint32_t a_hiB = base + 0 * TILE_B;
        const uint32_t a_loB = base + 1 * TILE_B;
        const uint32_t b_hiB = base + 2 * TILE_B;
        const uint32_t b_loB = base + 3 * TILE_B;

#pragma unroll
        for (int ks = 0; ks < 2; ks++) {
            const int kb = ks * 32;

            // A fragments for this k16 step (32 regs live)
            uint32_t ah[4][4], al[4][4];
            const int ar = warp_m * 64 + (lane & 15);
            const uint32_t acol = kb + ((lane >> 4) << 4);
#pragma unroll
            for (int mi = 0; mi < 4; mi++) {
                uint32_t off = (uint32_t)(ar + mi * 16) * ROWB + acol;
                LDMATRIX_X4(ah[mi][0], ah[mi][1], ah[mi][2], ah[mi][3], a_hiB + off);
                LDMATRIX_X4(al[mi][0], al[mi][1], al[mi][2], al[mi][3], a_loB + off);
            }

            // B fragments per 16-col group, consumed immediately (8 regs live)
            const int brr = warp_n * 64 + ((lane >> 4) & 1) * 8 + (lane & 7);
            const uint32_t bcol = kb + ((lane >> 3) & 1) * 16;
#pragma unroll
            for (int nb = 0; nb < 4; nb++) {
                uint32_t bh[2][2], bl[2][2];
                uint32_t off = (uint32_t)(brr + nb * 16) * ROWB + bcol;
                LDMATRIX_X4(bh[0][0], bh[0][1], bh[1][0], bh[1][1], b_hiB + off);
                LDMATRIX_X4(bl[0][0], bl[0][1], bl[1][0], bl[1][1], b_loB + off);
#pragma unroll
                for (int t = 0; t < 2; t++) {
                    int ni = nb * 2 + t;
#pragma unroll
                    for (int mi = 0; mi < 4; mi++) {
                        MMA_BF16(acc[mi][ni], ah[mi], bh[t]);
                        MMA_BF16(acc[mi][ni], ah[mi], bl[t]);
                        MMA_BF16(acc[mi][ni], al[mi], bh[t]);
                    }
                }
            }
        }
    }

    // ---- epilogue (no smem use) ----
#pragma unroll
    for (int mi = 0; mi < 4; mi++) {
        int r = row0 + warp_m * 64 + mi * 16 + (lane >> 2);
#pragma unroll
        for (int ni = 0; ni < 8; ni++) {
            int c = col0 + warp_n * 64 + ni * 8 + (lane & 3) * 2;
            if (Cf) {
                *(float2*)(Cf + (size_t)r * N + c) =
                    make_float2(acc[mi][ni][0], acc[mi][ni][1]);
                *(float2*)(Cf + (size_t)(r + 8) * N + c) =
                    make_float2(acc[mi][ni][2], acc[mi][ni][3]);
            } else {
#pragma unroll
                for (int rr = 0; rr < 2; rr++) {
                    float v0 = acc[mi][ni][rr*2], v1 = acc[mi][ni][rr*2+1];
                    __nv_bfloat162 ph, pl;
                    ph.x = __float2bfloat16(v0);
                    ph.y = __float2bfloat16(v1);
                    pl.x = __float2bfloat16(v0 - __bfloat162float(ph.x));
                    pl.y = __float2bfloat16(v1 - __bfloat162float(ph.y));
                    size_t off = (size_t)(r + rr * 8) * N + c;
                    *(__nv_bfloat162*)(Chi + off) = ph;
                    *(__nv_bfloat162*)(Clo + off) = pl;
                }
            }
        }
    }
}

// Fused QKV: z selects weight set; z=2 (V) writes bf16 hi/lo directly.
__global__ __launch_bounds__(GTHREADS, 2)
void gemm_qkv() {
    extern __shared__ char smem[];
    const int z = blockIdx.z;
    if (z == 0)
        gemm_body(g_xhi, g_xlo, g_wqhi, g_wqlo, g_q, nullptr, nullptr,
                  DMODEL, DMODEL, smem);
    else if (z == 1)
        gemm_body(g_xhi, g_xlo, g_wkhi, g_wklo, g_k, nullptr, nullptr,
                  DMODEL, DMODEL, smem);
    else
        gemm_body(g_xhi, g_xlo, g_wvhi, g_wvlo, nullptr, g_vhi, g_vlo,
                  DMODEL, DMODEL, smem);
}

// Output projection
__global__ __launch_bounds__(GTHREADS, 2)
void gemm_out(float* __restrict__ out) {
    extern __shared__ char smem[];
    gemm_body(g_ohi, g_olo, g_wohi, g_wolo, out, nullptr, nullptr,
              DMODEL, DMODEL, smem);
}

// ---------------------------------------------------------------------------
// Tensor-core flash attention (causal, bf16 hi/lo split, fp32 accum).
// ---------------------------------------------------------------------------
#define FROWB 272
#define FTILE (64 * FROWB)
#define SQH 0
#define SQL (1 * FTILE)
#define SKH (2 * FTILE)
#define SKL (3 * FTILE)
#define SVH (4 * FTILE)
#define SVL (5 * FTILE)
#define FA_SMEM (6 * FTILE)      // 104448 B

__global__ __launch_bounds__(128)
void flash_attn_tc() {
    extern __shared__ char sm[];
    const uint32_t sb = smem_to_u32(sm);
    const int tid  = threadIdx.x;
    const int lane = tid & 31;
    const int warp = tid >> 5;

    const int mb = (int)gridDim.x - 1 - (int)blockIdx.x;
    const int bh = blockIdx.y;
    const int b  = bh >> 4;
    const int h  = bh & 15;
    const float scale = 0.08838834764831845f;

    const size_t hbase = (size_t)b * SEQ * DMODEL + (size_t)h * HDIM;

    {
        const size_t q0 = hbase + (size_t)mb * 64 * DMODEL;
        for (int i = tid; i < 1024; i += 128) {
            int r = i >> 4, c = i & 15;
            uint32_t d = sb + r * FROWB + c * 16;
            size_t g = q0 + (size_t)r * DMODEL + c * 8;
            CP_ASYNC_16(d + SQH, g_qhi + g);
            CP_ASYNC_16(d + SQL, g_qlo + g);
        }
        CP_ASYNC_COMMIT();
    }

    const int r0 = lane >> 2;
    float m0 = -INFINITY, m1 = -INFINITY, l0 = 0.f, l1 = 0.f;
    float oacc[16][4];
#pragma unroll
    for (int nb = 0; nb < 16; nb++)
#pragma unroll
        for (int e = 0; e < 4; e++) oacc[nb][e] = 0.f;

    for (int jb = 0; jb <= mb; jb++) {
        {
            const size_t kv0 = hbase + (size_t)jb * 64 * DMODEL;
            for (int i = tid; i < 1024; i += 128) {
                int r = i >> 4, c = i & 15;
                uint32_t d = sb + r * FROWB + c * 16;
                size_t g = kv0 + (size_t)r * DMODEL + c * 8;
                CP_ASYNC_16(d + SKH, g_khi + g);
                CP_ASYNC_16(d + SKL, g_klo + g);
                CP_ASYNC_16(d + SVH, g_vhi + g);
                CP_ASYNC_16(d + SVL, g_vlo + g);
            }
            CP_ASYNC_COMMIT();
            CP_ASYNC_WAIT_0();
            __syncthreads();
        }

        float sacc[8][4];
#pragma unroll
        for (int j = 0; j < 8; j++)
#pragma unroll
            for (int e = 0; e < 4; e++) sacc[j][e] = 0.f;

#pragma unroll
        for (int ks = 0; ks < 8; ks++) {
            const int kb = ks * 32;
            uint32_t aqh[4], aql[4];
            uint32_t aaddr = sb + (uint32_t)(warp * 16 + (lane & 15)) * FROWB
                           + kb + ((lane >> 4) << 4);
            LDMATRIX_X4(aqh[0], aqh[1], aqh[2], aqh[3], aaddr + SQH);
            LDMATRIX_X4(aql[0], aql[1], aql[2], aql[3], aaddr + SQL);
#pragma unroll
            for (int nsl = 0; nsl < 4; nsl++) {
                uint32_t bkh[2][2], bkl[2][2];
                uint32_t baddr = sb
                    + (uint32_t)(nsl * 16 + ((lane >> 4) & 1) * 8 + (lane & 7)) * FROWB
                    + kb + ((lane >> 3) & 1) * 16;
                LDMATRIX_X4(bkh[0][0], bkh[0][1], bkh[1][0], bkh[1][1], baddr + SKH);
                LDMATRIX_X4(bkl[0][0], bkl[0][1], bkl[1][0], bkl[1][1], baddr + SKL);
#pragma unroll
                for (int t = 0; t < 2; t++) {
                    int j = nsl * 2 + t;
                    MMA_BF16(sacc[j], aqh, bkh[t]);
                    MMA_BF16(sacc[j], aqh, bkl[t]);
                    MMA_BF16(sacc[j], aql, bkh[t]);
                }
            }
        }

#pragma unroll
        for (int j = 0; j < 8; j++)
#pragma unroll
            for (int e = 0; e < 4; e++) sacc[j][e] *= scale;

        if (jb == mb) {
            const int row0 = warp * 16 + r0;
            const int row1 = row0 + 8;
#pragma unroll
            for (int j = 0; j < 8; j++) {
                int c0 = j * 8 + (lane & 3) * 2;
                if (c0     > row0) sacc[j][0] = -INFINITY;
                if (c0 + 1 > row0) sacc[j][1] = -INFINITY;
                if (c0     > row1) sacc[j][2] = -INFINITY;
                if (c0 + 1 > row1) sacc[j][3] = -INFINITY;
            }
        }

        float mn0 = -INFINITY, mn1 = -INFINITY;
#pragma unroll
        for (int j = 0; j < 8; j++) {
            mn0 = fmaxf(mn0, fmaxf(sacc[j][0], sacc[j][1]));
            mn1 = fmaxf(mn1, fmaxf(sacc[j][2], sacc[j][3]));
        }
        mn0 = fmaxf(mn0, __shfl_xor_sync(0xffffffffu, mn0, 1));
        mn0 = fmaxf(mn0, __shfl_xor_sync(0xffffffffu, mn0, 2));
        mn1 = fmaxf(mn1, __shfl_xor_sync(0xffffffffu, mn1, 1));
        mn1 = fmaxf(mn1, __shfl_xor_sync(0xffffffffu, mn1, 2));
        mn0 = fmaxf(mn0, m0);
        mn1 = fmaxf(mn1, m1);

        float alpha0 = __expf(m0 - mn0);
        float alpha1 = __expf(m1 - mn1);
        m0 = mn0; m1 = mn1;
        l0 *= alpha0; l1 *= alpha1;
#pragma unroll
        for (int nb = 0; nb < 16; nb++) {
            oacc[nb][0] *= alpha0; oacc[nb][1] *= alpha0;
            oacc[nb][2] *= alpha1; oacc[nb][3] *= alpha1;
        }

        float rs0 = 0.f, rs1 = 0.f;
#pragma unroll
        for (int j = 0; j < 8; j++) {
            float p0 = __expf(sacc[j][0] - mn0);
            float p1 = __expf(sacc[j][1] - mn0);
            float p2 = __expf(sacc[j][2] - mn1);
            float p3 = __expf(sacc[j][3] - mn1);
            sacc[j][0] = p0; sacc[j][1] = p1; sacc[j][2] = p2; sacc[j][3] = p3;
            rs0 += p0 + p1; rs1 += p2 + p3;
        }
        rs0 += __shfl_xor_sync(0xffffffffu, rs0, 1);
        rs0 += __shfl_xor_sync(0xffffffffu, rs0, 2);
        rs1 += __shfl_xor_sync(0xffffffffu, rs1, 1);
        rs1 += __shfl_xor_sync(0xffffffffu, rs1, 2);
        l0 += rs0; l1 += rs1;

        uint32_t aph[4][4], apl[4][4];
#pragma unroll
        for (int kb2 = 0; kb2 < 4; kb2++) {
            int j = kb2 * 2;
#pragma unroll
            for (int q = 0; q < 4; q++) {
                int jj = j + (q >> 1);
                int e0 = (q & 1) * 2;
                float p0 = sacc[jj][e0], p1 = sacc[jj][e0 + 1];
                float h0 = __bfloat162float(__float2bfloat16(p0));
                float h1 = __bfloat162float(__float2bfloat16(p1));
                PACK_BF16X2(aph[kb2][q], h1, h0);
                PACK_BF16X2(apl[kb2][q], p1 - h1, p0 - h0);
            }
        }

#pragma unroll
        for (int kb2 = 0; kb2 < 4; kb2++) {
#pragma unroll
            for (int ns2 = 0; ns2 < 8; ns2++) {
                uint32_t bvh[2][2], bvl[2][2];
                uint32_t vaddr = sb
                    + (uint32_t)(kb2 * 16 + (lane & 7) + ((lane >> 3) & 1) * 8) * FROWB
                    + ns2 * 32 + ((lane >> 4) & 1) * 16;
                LDMATRIX_X4_TRANS(bvh[0][0], bvh[0][1], bvh[1][0], bvh[1][1], vaddr + SVH);
                LDMATRIX_X4_TRANS(bvl[0][0], bvl[0][1], bvl[1][0], bvl[1][1], vaddr + SVL);
#pragma unroll
                for (int t = 0; t < 2; t++) {
                    int nb = ns2 * 2 + t;
                    MMA_BF16(oacc[nb], aph[kb2], bvh[t]);
                    MMA_BF16(oacc[nb], apl[kb2], bvh[t]);
                    MMA_BF16(oacc[nb], aph[kb2], bvl[t]);
                }
            }
        }
        __syncthreads();
    }

    const float inv0 = 1.0f / l0;
    const float inv1 = 1.0f / l1;
    const size_t obase = hbase + (size_t)(mb * 64 + warp * 16) * DMODEL;
#pragma unroll
    for (int nb = 0; nb < 16; nb++) {
        int c = nb * 8 + (lane & 3) * 2;
#pragma unroll
        for (int rr = 0; rr < 2; rr++) {
            float v0 = oacc[nb][rr*2]     * (rr ? inv1 : inv0);
            float v1 = oacc[nb][rr*2 + 1] * (rr ? inv1 : inv0);
            __nv_bfloat162 ph, pl;
            ph.x = __float2bfloat16(v0);
            ph.y = __float2bfloat16(v1);
            pl.x = __float2bfloat16(v0 - __bfloat162float(ph.x));
            pl.y = __float2bfloat16(v1 - __bfloat162float(ph.y));
            size_t off = obase + (size_t)(r0 + rr * 8) * DMODEL + c;
            *(__nv_bfloat162*)(g_ohi + off) = ph;
            *(__nv_bfloat162*)(g_olo + off) = pl;
        }
    }
}

// ---------------------------------------------------------------------------
// Launch. Order: 1 x-split, 2 w-split, 3 rope_table, 4 gemm_qkv,
//                5 rope_split, 6 flash (ncu target), 7 gemm_out.
// ---------------------------------------------------------------------------
extern "C" void kernel_launch(void* const* d_in, const int* in_sizes, int n_in,
                              void* d_out, int out_size) {
    const float* x  = (const float*)d_in[0];
    const float* wq = (const float*)d_in[1];
    const float* wk = (const float*)d_in[2];
    const float* wv = (const float*)d_in[3];
    const float* wo = (const float*)d_in[4];
    float* out = (float*)d_out;

    __nv_bfloat16 *xhi, *xlo;
    cudaGetSymbolAddress((void**)&xhi, g_xhi);
    cudaGetSymbolAddress((void**)&xlo, g_xlo);

    const size_t nx = (size_t)BT * DMODEL;        // 16.7M
    const size_t nw = (size_t)DMODEL * DMODEL;    // 4.19M

    // 1: x split   2: all weight splits (fused)
    split_bf16_v8<<<(int)(nx / 2048), 256>>>(x, xhi, xlo, nx);
    split_weights<<<dim3((unsigned)(nw / 2048), 4), 256>>>(wq, wk, wv, wo);

    // 3: RoPE table
    rope_table_kernel<<<(SEQ * 64 + 255) / 256, 256>>>();

    // 4: fused QKV projections
    cudaFuncSetAttribute(gemm_qkv,
                         cudaFuncAttributeMaxDynamicSharedMemorySize, GEMM_SMEM);
    gemm_qkv<<<dim3(DMODEL / BN, BT / BM, 3), GTHREADS, GEMM_SMEM>>>();

    // 5: RoPE + q/k split
    {
        size_t total = (size_t)BT * NHEAD * (HDIM / 2);
        rope_split_kernel<<<(int)((total + 255) / 256), 256>>>();
    }

    // 6: tensor-core flash (ncu target)
    cudaFuncSetAttribute(flash_attn_tc,
                         cudaFuncAttributeMaxDynamicSharedMemorySize, FA_SMEM);
    flash_attn_tc<<<dim3(SEQ / 64, BATCH * NHEAD), 128, FA_SMEM>>>();

    // 7: output projection
    cudaFuncSetAttribute(gemm_out,
                         cudaFuncAttributeMaxDynamicSharedMemorySize, GEMM_SMEM);
    gemm_out<<<dim3(DMODEL / BN, BT / BM, 1), GTHREADS, GEMM_SMEM>>>(out);
}

// round 16
// speedup vs baseline: 1.0225x; 1.0225x over previous
#include <cuda_runtime.h>
#include <cuda_bf16.h>
#include <math.h>
#include <stdint.h>

// ---------------------------------------------------------------------------
// Problem constants
// ---------------------------------------------------------------------------
#define BATCH   4
#define SEQ     2048
#define DMODEL  2048
#define NHEAD   16
#define HDIM    128
#define BT      (BATCH * SEQ)   // 8192

__device__ __forceinline__ uint32_t smem_to_u32(const void* smem_ptr) {
    uint32_t addr;
    asm("{ .reg .u64 tmp; cvta.to.shared.u64 tmp, %1; cvt.u32.u64 %0, tmp; }"
        : "=r"(addr) : "l"(smem_ptr));
    return addr;
}

#define CP_ASYNC_16(dst_u32, src_ptr) \
    asm volatile("cp.async.cg.shared.global [%0], [%1], 16;" \
        :: "r"(dst_u32), "l"(src_ptr) : "memory")
#define CP_ASYNC_COMMIT() asm volatile("cp.async.commit_group;" ::: "memory")
#define CP_ASYNC_WAIT_1() asm volatile("cp.async.wait_group 1;" ::: "memory")
#define CP_ASYNC_WAIT_0() asm volatile("cp.async.wait_group 0;" ::: "memory")

#define LDMATRIX_X4(r0, r1, r2, r3, addr) \
    asm volatile("ldmatrix.sync.aligned.m8n8.x4.shared.b16 {%0,%1,%2,%3}, [%4];" \
        : "=r"(r0), "=r"(r1), "=r"(r2), "=r"(r3) : "r"(addr))

#define LDMATRIX_X4_TRANS(r0, r1, r2, r3, addr) \
    asm volatile("ldmatrix.sync.aligned.m8n8.x4.trans.shared.b16 {%0,%1,%2,%3}, [%4];" \
        : "=r"(r0), "=r"(r1), "=r"(r2), "=r"(r3) : "r"(addr))

#define MMA_BF16(c, a, b) \
    asm volatile( \
        "mma.sync.aligned.m16n8k16.row.col.f32.bf16.bf16.f32 " \
        "{%0,%1,%2,%3}, {%4,%5,%6,%7}, {%8,%9}, {%0,%1,%2,%3};" \
        : "+f"((c)[0]), "+f"((c)[1]), "+f"((c)[2]), "+f"((c)[3]) \
        : "r"((a)[0]), "r"((a)[1]), "r"((a)[2]), "r"((a)[3]), \
          "r"((b)[0]), "r"((b)[1]))

#define PACK_BF16X2(d, hi_f, lo_f) \
    asm("cvt.rn.bf16x2.f32 %0, %1, %2;" : "=r"(d) : "f"(hi_f), "f"(lo_f))

// ---------------------------------------------------------------------------
// Scratch (allocation-free rule: __device__ globals)
// ---------------------------------------------------------------------------
__device__ float g_q[(size_t)BT * DMODEL];
__device__ float g_k[(size_t)BT * DMODEL];
__device__ float2 g_rope_tab[SEQ * 64];

__device__ __nv_bfloat16 g_xhi[(size_t)BT * DMODEL];
__device__ __nv_bfloat16 g_xlo[(size_t)BT * DMODEL];
__device__ __nv_bfloat16 g_ohi[(size_t)BT * DMODEL];
__device__ __nv_bfloat16 g_olo[(size_t)BT * DMODEL];
__device__ __nv_bfloat16 g_wqhi[(size_t)DMODEL * DMODEL];
__device__ __nv_bfloat16 g_wqlo[(size_t)DMODEL * DMODEL];
__device__ __nv_bfloat16 g_wkhi[(size_t)DMODEL * DMODEL];
__device__ __nv_bfloat16 g_wklo[(size_t)DMODEL * DMODEL];
__device__ __nv_bfloat16 g_wvhi[(size_t)DMODEL * DMODEL];
__device__ __nv_bfloat16 g_wvlo[(size_t)DMODEL * DMODEL];
__device__ __nv_bfloat16 g_wohi[(size_t)DMODEL * DMODEL];
__device__ __nv_bfloat16 g_wolo[(size_t)DMODEL * DMODEL];

__device__ __nv_bfloat16 g_qhi[(size_t)BT * DMODEL];
__device__ __nv_bfloat16 g_qlo[(size_t)BT * DMODEL];
__device__ __nv_bfloat16 g_khi[(size_t)BT * DMODEL];
__device__ __nv_bfloat16 g_klo[(size_t)BT * DMODEL];
__device__ __nv_bfloat16 g_vhi[(size_t)BT * DMODEL];
__device__ __nv_bfloat16 g_vlo[(size_t)BT * DMODEL];

// ---------------------------------------------------------------------------
// Vectorized fp32 -> (bf16 hi, bf16 lo) split: 8 elems/thread
// ---------------------------------------------------------------------------
__device__ __forceinline__
void split8(const float* __restrict__ src,
            __nv_bfloat16* __restrict__ hi, __nv_bfloat16* __restrict__ lo,
            size_t i8) {
    float4 a = *(const float4*)(src + i8);
    float4 b = *(const float4*)(src + i8 + 4);
    float v[8] = {a.x, a.y, a.z, a.w, b.x, b.y, b.z, b.w};
    __nv_bfloat162 ph[4], pl[4];
#pragma unroll
    for (int j = 0; j < 4; j++) {
        __nv_bfloat16 h0 = __float2bfloat16(v[2*j]);
        __nv_bfloat16 h1 = __float2bfloat16(v[2*j+1]);
        ph[j].x = h0; ph[j].y = h1;
        pl[j].x = __float2bfloat16(v[2*j]   - __bfloat162float(h0));
        pl[j].y = __float2bfloat16(v[2*j+1] - __bfloat162float(h1));
    }
    *(uint4*)(hi + i8) = *(uint4*)ph;
    *(uint4*)(lo + i8) = *(uint4*)pl;
}

__global__ __launch_bounds__(256)
void split_bf16_v8(const float* __restrict__ src,
                   __nv_bfloat16* __restrict__ hi, __nv_bfloat16* __restrict__ lo,
                   size_t n) {
    size_t i8 = ((size_t)blockIdx.x * 256 + threadIdx.x) * 8;
    if (i8 >= n) return;
    split8(src, hi, lo, i8);
}

// Fused weight splits: blockIdx.y selects which weight (0=q,1=k,2=v,3=o).
__global__ __launch_bounds__(256)
void split_weights(const float* __restrict__ wq, const float* __restrict__ wk,
                   const float* __restrict__ wv, const float* __restrict__ wo) {
    const size_t nw = (size_t)DMODEL * DMODEL;
    size_t i8 = ((size_t)blockIdx.x * 256 + threadIdx.x) * 8;
    if (i8 >= nw) return;
    switch (blockIdx.y) {
        case 0: split8(wq, g_wqhi, g_wqlo, i8); break;
        case 1: split8(wk, g_wkhi, g_wklo, i8); break;
        case 2: split8(wv, g_wvhi, g_wvlo, i8); break;
        default: split8(wo, g_wohi, g_wolo, i8); break;
    }
}

// ---------------------------------------------------------------------------
// RoPE table in double precision (immune to --use_fast_math)
// ---------------------------------------------------------------------------
__global__ __launch_bounds__(256)
void rope_table_kernel() {
    int idx = blockIdx.x * blockDim.x + threadIdx.x;
    if (idx >= SEQ * 64) return;
    int i = idx & 63;
    int t = idx >> 6;
    float inv_freq = (float)exp(-log(10000.0) * ((double)i / 64.0));
    float ang_f = (float)t * inv_freq;
    double ang = (double)ang_f;
    g_rope_tab[idx] = make_float2((float)cos(ang), (float)sin(ang));
}

// ---------------------------------------------------------------------------
// RoPE + bf16 hi/lo split for q and k (fused)
// ---------------------------------------------------------------------------
__global__ __launch_bounds__(256)
void rope_split_kernel() {
    const size_t total = (size_t)BT * NHEAD * (HDIM / 2);
    size_t idx = (size_t)blockIdx.x * blockDim.x + threadIdx.x;
    if (idx >= total) return;

    int i  = (int)(idx & 63);
    int h  = (int)((idx >> 6) & (NHEAD - 1));
    int bt = (int)(idx >> 10);
    int t  = bt & (SEQ - 1);

    float2 cs = g_rope_tab[t * 64 + i];
    float c = cs.x, s = cs.y;

    size_t base = (size_t)bt * DMODEL + h * HDIM + i;

    float q1 = g_q[base], q2 = g_q[base + 64];
    float qa = q1 * c - q2 * s;
    float qb = q2 * c + q1 * s;
    __nv_bfloat16 qah = __float2bfloat16(qa);
    __nv_bfloat16 qbh = __float2bfloat16(qb);
    g_qhi[base]      = qah; g_qlo[base]      = __float2bfloat16(qa - __bfloat162float(qah));
    g_qhi[base + 64] = qbh; g_qlo[base + 64] = __float2bfloat16(qb - __bfloat162float(qbh));

    float k1 = g_k[base], k2 = g_k[base + 64];
    float ka = k1 * c - k2 * s;
    float kb = k2 * c + k1 * s;
    __nv_bfloat16 kah = __float2bfloat16(ka);
    __nv_bfloat16 kbh = __float2bfloat16(kb);
    g_khi[base]      = kah; g_klo[base]      = __float2bfloat16(ka - __bfloat162float(kah));
    g_khi[base + 64] = kbh; g_klo[base + 64] = __float2bfloat16(kb - __bfloat162float(kbh));
}

// ---------------------------------------------------------------------------
// bf16-split GEMM — 128-thread CTA, 4 warps (2x2), 64x64 warp tile, 2 CTAs/SM.
// 2-stage pipeline, validated R14 sync ordering and R14 grouped fragment loads
// (R15's interleaved variant was net-negative; reverted).
// ---------------------------------------------------------------------------
#define BM 128
#define BN 128
#define BK 32
#define ROWB 80
#define TILE_B (128 * ROWB)
#define STAGE_B (4 * TILE_B)          // 40960 B
#define GEMM_SMEM (2 * STAGE_B)       // 81920 B
#define GTHREADS 128

__device__ __forceinline__
void gemm_body(const __nv_bfloat16* __restrict__ Ahi,
               const __nv_bfloat16* __restrict__ Alo,
               const __nv_bfloat16* __restrict__ Bhi,
               const __nv_bfloat16* __restrict__ Blo,
               float* __restrict__ Cf,
               __nv_bfloat16* __restrict__ Chi,
               __nv_bfloat16* __restrict__ Clo,
               int N, int K, char* smem) {
    const uint32_t sb = smem_to_u32(smem);
    const int tid  = threadIdx.x;
    const int lane = tid & 31;
    const int wid  = tid >> 5;
    const int warp_m = wid & 1;
    const int warp_n = wid >> 1;

    const int row0 = blockIdx.y * BM;
    const int col0 = blockIdx.x * BN;

    float acc[4][8][4];
#pragma unroll
    for (int mi = 0; mi < 4; mi++)
#pragma unroll
        for (int ni = 0; ni < 8; ni++)
#pragma unroll
            for (int e = 0; e < 4; e++) acc[mi][ni][e] = 0.f;

    const int r_ld  = tid >> 2;
    const int c_ld  = (tid & 3) * 16;
    const int ke_ld = (tid & 3) * 8;

    // ---- prologue: stage 0 ----
    {
#pragma unroll
        for (int rnd = 0; rnd < 4; rnd++) {
            int r = r_ld + rnd * 32;
            uint32_t d = sb + r * ROWB + c_ld;
            size_t ga = (size_t)(row0 + r) * K + ke_ld;
            size_t gb = (size_t)(col0 + r) * K + ke_ld;
            CP_ASYNC_16(d + 0 * TILE_B, Ahi + ga);
            CP_ASYNC_16(d + 1 * TILE_B, Alo + ga);
            CP_ASYNC_16(d + 2 * TILE_B, Bhi + gb);
            CP_ASYNC_16(d + 3 * TILE_B, Blo + gb);
        }
        CP_ASYNC_COMMIT();
    }

    const int niter = K / BK;
    for (int kt = 0; kt < niter; kt++) {
        __syncthreads();               // readers of buffer (kt-1)&1 done

        if (kt + 1 < niter) {
            const int k0 = (kt + 1) * BK;
            const uint32_t base = sb + ((kt + 1) & 1) * STAGE_B;
#pragma unroll
            for (int rnd = 0; rnd < 4; rnd++) {
                int r = r_ld + rnd * 32;
                uint32_t d = base + r * ROWB + c_ld;
                size_t ga = (size_t)(row0 + r) * K + k0 + ke_ld;
                size_t gb = (size_t)(col0 + r) * K + k0 + ke_ld;
                CP_ASYNC_16(d + 0 * TILE_B, Ahi + ga);
                CP_ASYNC_16(d + 1 * TILE_B, Alo + ga);
                CP_ASYNC_16(d + 2 * TILE_B, Bhi + gb);
                CP_ASYNC_16(d + 3 * TILE_B, Blo + gb);
            }
        }
        CP_ASYNC_COMMIT();
        CP_ASYNC_WAIT_1();             // own stage-kt group complete
        __syncthreads();               // publish all threads' stage-kt data

        const uint32_t base  = sb + (kt & 1) * STAGE_B;
        const uint32_t a_hiB = base + 0 * TILE_B;
        const uint32_t a_loB = base + 1 * TILE_B;
        const uint32_t b_hiB = base + 2 * TILE_B;
        const uint32_t b_loB = base + 3 * TILE_B;

#pragma unroll
        for (int ks = 0; ks < 2; ks++) {
            const int kb = ks * 32;

            uint32_t ah[4][4], al[4][4], bh[8][2], bl[8][2];
            const int ar = warp_m * 64 + (lane & 15);
            const uint32_t acol = kb + ((lane >> 4) << 4);
#pragma unroll
            for (int mi = 0; mi < 4; mi++) {
                uint32_t off = (uint32_t)(ar + mi * 16) * ROWB + acol;
                LDMATRIX_X4(ah[mi][0], ah[mi][1], ah[mi][2], ah[mi][3], a_hiB + off);
                LDMATRIX_X4(al[mi][0], al[mi][1], al[mi][2], al[mi][3], a_loB + off);
            }
            const int brr = warp_n * 64 + ((lane >> 4) & 1) * 8 + (lane & 7);
            const uint32_t bcol = kb + ((lane >> 3) & 1) * 16;
#pragma unroll
            for (int nb = 0; nb < 4; nb++) {
                uint32_t off = (uint32_t)(brr + nb * 16) * ROWB + bcol;
                LDMATRIX_X4(bh[2*nb][0], bh[2*nb][1], bh[2*nb+1][0], bh[2*nb+1][1],
                            b_hiB + off);
                LDMATRIX_X4(bl[2*nb][0], bl[2*nb][1], bl[2*nb+1][0], bl[2*nb+1][1],
                            b_loB + off);
            }
#pragma unroll
            for (int mi = 0; mi < 4; mi++)
#pragma unroll
                for (int ni = 0; ni < 8; ni++) {
                    MMA_BF16(acc[mi][ni], ah[mi], bh[ni]);
                    MMA_BF16(acc[mi][ni], ah[mi], bl[ni]);
                    MMA_BF16(acc[mi][ni], al[mi], bh[ni]);
                }
        }
    }

    // ---- epilogue (no smem use) ----
#pragma unroll
    for (int mi = 0; mi < 4; mi++) {
        int r = row0 + warp_m * 64 + mi * 16 + (lane >> 2);
#pragma unroll
        for (int ni = 0; ni < 8; ni++) {
            int c = col0 + warp_n * 64 + ni * 8 + (lane & 3) * 2;
            if (Cf) {
                *(float2*)(Cf + (size_t)r * N + c) =
                    make_float2(acc[mi][ni][0], acc[mi][ni][1]);
                *(float2*)(Cf + (size_t)(r + 8) * N + c) =
                    make_float2(acc[mi][ni][2], acc[mi][ni][3]);
            } else {
#pragma unroll
                for (int rr = 0; rr < 2; rr++) {
                    float v0 = acc[mi][ni][rr*2], v1 = acc[mi][ni][rr*2+1];
                    __nv_bfloat162 ph, pl;
                    ph.x = __float2bfloat16(v0);
                    ph.y = __float2bfloat16(v1);
                    pl.x = __float2bfloat16(v0 - __bfloat162float(ph.x));
                    pl.y = __float2bfloat16(v1 - __bfloat162float(ph.y));
                    size_t off = (size_t)(r + rr * 8) * N + c;
                    *(__nv_bfloat162*)(Chi + off) = ph;
                    *(__nv_bfloat162*)(Clo + off) = pl;
                }
            }
        }
    }
}

// Fused QKV: z selects weight set; z=2 (V) writes bf16 hi/lo directly.
__global__ __launch_bounds__(GTHREADS, 2)
void gemm_qkv() {
    extern __shared__ char smem[];
    const int z = blockIdx.z;
    if (z == 0)
        gemm_body(g_xhi, g_xlo, g_wqhi, g_wqlo, g_q, nullptr, nullptr,
                  DMODEL, DMODEL, smem);
    else if (z == 1)
        gemm_body(g_xhi, g_xlo, g_wkhi, g_wklo, g_k, nullptr, nullptr,
                  DMODEL, DMODEL, smem);
    else
        gemm_body(g_xhi, g_xlo, g_wvhi, g_wvlo, nullptr, g_vhi, g_vlo,
                  DMODEL, DMODEL, smem);
}

// Output projection
__global__ __launch_bounds__(GTHREADS, 2)
void gemm_out(float* __restrict__ out) {
    extern __shared__ char smem[];
    gemm_body(g_ohi, g_olo, g_wohi, g_wolo, out, nullptr, nullptr,
              DMODEL, DMODEL, smem);
}

// ---------------------------------------------------------------------------
// Tensor-core flash attention (causal, bf16 hi/lo split, fp32 accum).
// R16: 2 CTAs/SM (2x104448B smem fits 227KB; regs<=256 at 2x128thr) —
// co-resident CTA overlaps one CTA's KV-load wait with the other's MMAs.
// ---------------------------------------------------------------------------
#define FROWB 272
#define FTILE (64 * FROWB)
#define SQH 0
#define SQL (1 * FTILE)
#define SKH (2 * FTILE)
#define SKL (3 * FTILE)
#define SVH (4 * FTILE)
#define SVL (5 * FTILE)
#define FA_SMEM (6 * FTILE)      // 104448 B

__global__ __launch_bounds__(128, 2)
void flash_attn_tc() {
    extern __shared__ char sm[];
    const uint32_t sb = smem_to_u32(sm);
    const int tid  = threadIdx.x;
    const int lane = tid & 31;
    const int warp = tid >> 5;

    const int mb = (int)gridDim.x - 1 - (int)blockIdx.x;
    const int bh = blockIdx.y;
    const int b  = bh >> 4;
    const int h  = bh & 15;
    const float scale = 0.08838834764831845f;

    const size_t hbase = (size_t)b * SEQ * DMODEL + (size_t)h * HDIM;

    {
        const size_t q0 = hbase + (size_t)mb * 64 * DMODEL;
        for (int i = tid; i < 1024; i += 128) {
            int r = i >> 4, c = i & 15;
            uint32_t d = sb + r * FROWB + c * 16;
            size_t g = q0 + (size_t)r * DMODEL + c * 8;
            CP_ASYNC_16(d + SQH, g_qhi + g);
            CP_ASYNC_16(d + SQL, g_qlo + g);
        }
        CP_ASYNC_COMMIT();
    }

    const int r0 = lane >> 2;
    float m0 = -INFINITY, m1 = -INFINITY, l0 = 0.f, l1 = 0.f;
    float oacc[16][4];
#pragma unroll
    for (int nb = 0; nb < 16; nb++)
#pragma unroll
        for (int e = 0; e < 4; e++) oacc[nb][e] = 0.f;

    for (int jb = 0; jb <= mb; jb++) {
        {
            const size_t kv0 = hbase + (size_t)jb * 64 * DMODEL;
            for (int i = tid; i < 1024; i += 128) {
                int r = i >> 4, c = i & 15;
                uint32_t d = sb + r * FROWB + c * 16;
                size_t g = kv0 + (size_t)r * DMODEL + c * 8;
                CP_ASYNC_16(d + SKH, g_khi + g);
                CP_ASYNC_16(d + SKL, g_klo + g);
                CP_ASYNC_16(d + SVH, g_vhi + g);
                CP_ASYNC_16(d + SVL, g_vlo + g);
            }
            CP_ASYNC_COMMIT();
            CP_ASYNC_WAIT_0();
            __syncthreads();
        }

        float sacc[8][4];
#pragma unroll
        for (int j = 0; j < 8; j++)
#pragma unroll
            for (int e = 0; e < 4; e++) sacc[j][e] = 0.f;

#pragma unroll
        for (int ks = 0; ks < 8; ks++) {
            const int kb = ks * 32;
            uint32_t aqh[4], aql[4];
            uint32_t aaddr = sb + (uint32_t)(warp * 16 + (lane & 15)) * FROWB
                           + kb + ((lane >> 4) << 4);
            LDMATRIX_X4(aqh[0], aqh[1], aqh[2], aqh[3], aaddr + SQH);
            LDMATRIX_X4(aql[0], aql[1], aql[2], aql[3], aaddr + SQL);
#pragma unroll
            for (int nsl = 0; nsl < 4; nsl++) {
                uint32_t bkh[2][2], bkl[2][2];
                uint32_t baddr = sb
                    + (uint32_t)(nsl * 16 + ((lane >> 4) & 1) * 8 + (lane & 7)) * FROWB
                    + kb + ((lane >> 3) & 1) * 16;
                LDMATRIX_X4(bkh[0][0], bkh[0][1], bkh[1][0], bkh[1][1], baddr + SKH);
                LDMATRIX_X4(bkl[0][0], bkl[0][1], bkl[1][0], bkl[1][1], baddr + SKL);
#pragma unroll
                for (int t = 0; t < 2; t++) {
                    int j = nsl * 2 + t;
                    MMA_BF16(sacc[j], aqh, bkh[t]);
                    MMA_BF16(sacc[j], aqh, bkl[t]);
                    MMA_BF16(sacc[j], aql, bkh[t]);
                }
            }
        }

#pragma unroll
        for (int j = 0; j < 8; j++)
#pragma unroll
            for (int e = 0; e < 4; e++) sacc[j][e] *= scale;

        if (jb == mb) {
            const int row0 = warp * 16 + r0;
            const int row1 = row0 + 8;
#pragma unroll
            for (int j = 0; j < 8; j++) {
                int c0 = j * 8 + (lane & 3) * 2;
                if (c0     > row0) sacc[j][0] = -INFINITY;
                if (c0 + 1 > row0) sacc[j][1] = -INFINITY;
                if (c0     > row1) sacc[j][2] = -INFINITY;
                if (c0 + 1 > row1) sacc[j][3] = -INFINITY;
            }
        }

        float mn0 = -INFINITY, mn1 = -INFINITY;
#pragma unroll
        for (int j = 0; j < 8; j++) {
            mn0 = fmaxf(mn0, fmaxf(sacc[j][0], sacc[j][1]));
            mn1 = fmaxf(mn1, fmaxf(sacc[j][2], sacc[j][3]));
        }
        mn0 = fmaxf(mn0, __shfl_xor_sync(0xffffffffu, mn0, 1));
        mn0 = fmaxf(mn0, __shfl_xor_sync(0xffffffffu, mn0, 2));
        mn1 = fmaxf(mn1, __shfl_xor_sync(0xffffffffu, mn1, 1));
        mn1 = fmaxf(mn1, __shfl_xor_sync(0xffffffffu, mn1, 2));
        mn0 = fmaxf(mn0, m0);
        mn1 = fmaxf(mn1, m1);

        float alpha0 = __expf(m0 - mn0);
        float alpha1 = __expf(m1 - mn1);
        m0 = mn0; m1 = mn1;
        l0 *= alpha0; l1 *= alpha1;
#pragma unroll
        for (int nb = 0; nb < 16; nb++) {
            oacc[nb][0] *= alpha0; oacc[nb][1] *= alpha0;
            oacc[nb][2] *= alpha1; oacc[nb][3] *= alpha1;
        }

        float rs0 = 0.f, rs1 = 0.f;
#pragma unroll
        for (int j = 0; j < 8; j++) {
            float p0 = __expf(sacc[j][0] - mn0);
            float p1 = __expf(sacc[j][1] - mn0);
            float p2 = __expf(sacc[j][2] - mn1);
            float p3 = __expf(sacc[j][3] - mn1);
            sacc[j][0] = p0; sacc[j][1] = p1; sacc[j][2] = p2; sacc[j][3] = p3;
            rs0 += p0 + p1; rs1 += p2 + p3;
        }
        rs0 += __shfl_xor_sync(0xffffffffu, rs0, 1);
        rs0 += __shfl_xor_sync(0xffffffffu, rs0, 2);
        rs1 += __shfl_xor_sync(0xffffffffu, rs1, 1);
        rs1 += __shfl_xor_sync(0xffffffffu, rs1, 2);
        l0 += rs0; l1 += rs1;

        uint32_t aph[4][4], apl[4][4];
#pragma unroll
        for (int kb2 = 0; kb2 < 4; kb2++) {
            int j = kb2 * 2;
#pragma unroll
            for (int q = 0; q < 4; q++) {
                int jj = j + (q >> 1);
                int e0 = (q & 1) * 2;
                float p0 = sacc[jj][e0], p1 = sacc[jj][e0 + 1];
                float h0 = __bfloat162float(__float2bfloat16(p0));
                float h1 = __bfloat162float(__float2bfloat16(p1));
                PACK_BF16X2(aph[kb2][q], h1, h0);
                PACK_BF16X2(apl[kb2][q], p1 - h1, p0 - h0);
            }
        }

#pragma unroll
        for (int kb2 = 0; kb2 < 4; kb2++) {
#pragma unroll
            for (int ns2 = 0; ns2 < 8; ns2++) {
                uint32_t bvh[2][2], bvl[2][2];
                uint32_t vaddr = sb
                    + (uint32_t)(kb2 * 16 + (lane & 7) + ((lane >> 3) & 1) * 8) * FROWB
                    + ns2 * 32 + ((lane >> 4) & 1) * 16;
                LDMATRIX_X4_TRANS(bvh[0][0], bvh[0][1], bvh[1][0], bvh[1][1], vaddr + SVH);
                LDMATRIX_X4_TRANS(bvl[0][0], bvl[0][1], bvl[1][0], bvl[1][1], vaddr + SVL);
#pragma unroll
                for (int t = 0; t < 2; t++) {
                    int nb = ns2 * 2 + t;
                    MMA_BF16(oacc[nb], aph[kb2], bvh[t]);
                    MMA_BF16(oacc[nb], apl[kb2], bvh[t]);
                    MMA_BF16(oacc[nb], aph[kb2], bvl[t]);
                }
            }
        }
        __syncthreads();
    }

    const float inv0 = 1.0f / l0;
    const float inv1 = 1.0f / l1;
    const size_t obase = hbase + (size_t)(mb * 64 + warp * 16) * DMODEL;
#pragma unroll
    for (int nb = 0; nb < 16; nb++) {
        int c = nb * 8 + (lane & 3) * 2;
#pragma unroll
        for (int rr = 0; rr < 2; rr++) {
            float v0 = oacc[nb][rr*2]     * (rr ? inv1 : inv0);
            float v1 = oacc[nb][rr*2 + 1] * (rr ? inv1 : inv0);
            __nv_bfloat162 ph, pl;
            ph.x = __float2bfloat16(v0);
            ph.y = __float2bfloat16(v1);
            pl.x = __float2bfloat16(v0 - __bfloat162float(ph.x));
            pl.y = __float2bfloat16(v1 - __bfloat162float(ph.y));
            size_t off = obase + (size_t)(r0 + rr * 8) * DMODEL + c;
            *(__nv_bfloat162*)(g_ohi + off) = ph;
            *(__nv_bfloat162*)(g_olo + off) = pl;
        }
    }
}

// ---------------------------------------------------------------------------
// Launch. Order: 1 x-split, 2 w-split, 3 rope_table, 4 gemm_qkv,
//                5 rope_split, 6 flash (ncu target), 7 gemm_out.
// ---------------------------------------------------------------------------
extern "C" void kernel_launch(void* const* d_in, const int* in_sizes, int n_in,
                              void* d_out, int out_size) {
    const float* x  = (const float*)d_in[0];
    const float* wq = (const float*)d_in[1];
    const float* wk = (const float*)d_in[2];
    const float* wv = (const float*)d_in[3];
    const float* wo = (const float*)d_in[4];
    float* out = (float*)d_out;

    __nv_bfloat16 *xhi, *xlo;
    cudaGetSymbolAddress((void**)&xhi, g_xhi);
    cudaGetSymbolAddress((void**)&xlo, g_xlo);

    const size_t nx = (size_t)BT * DMODEL;        // 16.7M
    const size_t nw = (size_t)DMODEL * DMODEL;    // 4.19M

    // 1: x split   2: all weight splits (fused)
    split_bf16_v8<<<(int)(nx / 2048), 256>>>(x, xhi, xlo, nx);
    split_weights<<<dim3((unsigned)(nw / 2048), 4), 256>>>(wq, wk, wv, wo);

    // 3: RoPE table
    rope_table_kernel<<<(SEQ * 64 + 255) / 256, 256>>>();

    // 4: fused QKV projections
    cudaFuncSetAttribute(gemm_qkv,
                         cudaFuncAttributeMaxDynamicSharedMemorySize, GEMM_SMEM);
    gemm_qkv<<<dim3(DMODEL / BN, BT / BM, 3), GTHREADS, GEMM_SMEM>>>();

    // 5: RoPE + q/k split
    {
        size_t total = (size_t)BT * NHEAD * (HDIM / 2);
        rope_split_kernel<<<(int)((total + 255) / 256), 256>>>();
    }

    // 6: tensor-core flash (ncu target; 2 CTAs/SM)
    cudaFuncSetAttribute(flash_attn_tc,
                         cudaFuncAttributeMaxDynamicSharedMemorySize, FA_SMEM);
    flash_attn_tc<<<dim3(SEQ / 64, BATCH * NHEAD), 128, FA_SMEM>>>();

    // 7: output projection
    cudaFuncSetAttribute(gemm_out,
                         cudaFuncAttributeMaxDynamicSharedMemorySize, GEMM_SMEM);
    gemm_out<<<dim3(DMODEL / BN, BT / BM, 1), GTHREADS, GEMM_SMEM>>>(out);
}

// round 17
// speedup vs baseline: 1.0239x; 1.0013x over previous
#include <cuda_runtime.h>
#include <cuda_bf16.h>
#include <math.h>
#include <stdint.h>

// ---------------------------------------------------------------------------
// Problem constants
// ---------------------------------------------------------------------------
#define BATCH   4
#define SEQ     2048
#define DMODEL  2048
#define NHEAD   16
#define HDIM    128
#define BT      (BATCH * SEQ)   // 8192

__device__ __forceinline__ uint32_t smem_to_u32(const void* smem_ptr) {
    uint32_t addr;
    asm("{ .reg .u64 tmp; cvta.to.shared.u64 tmp, %1; cvt.u32.u64 %0, tmp; }"
        : "=r"(addr) : "l"(smem_ptr));
    return addr;
}

#define CP_ASYNC_16(dst_u32, src_ptr) \
    asm volatile("cp.async.cg.shared.global [%0], [%1], 16;" \
        :: "r"(dst_u32), "l"(src_ptr) : "memory")
#define CP_ASYNC_COMMIT() asm volatile("cp.async.commit_group;" ::: "memory")
#define CP_ASYNC_WAIT_1() asm volatile("cp.async.wait_group 1;" ::: "memory")
#define CP_ASYNC_WAIT_0() asm volatile("cp.async.wait_group 0;" ::: "memory")

#define LDMATRIX_X4(r0, r1, r2, r3, addr) \
    asm volatile("ldmatrix.sync.aligned.m8n8.x4.shared.b16 {%0,%1,%2,%3}, [%4];" \
        : "=r"(r0), "=r"(r1), "=r"(r2), "=r"(r3) : "r"(addr))

#define LDMATRIX_X4_TRANS(r0, r1, r2, r3, addr) \
    asm volatile("ldmatrix.sync.aligned.m8n8.x4.trans.shared.b16 {%0,%1,%2,%3}, [%4];" \
        : "=r"(r0), "=r"(r1), "=r"(r2), "=r"(r3) : "r"(addr))

#define MMA_BF16(c, a, b) \
    asm volatile( \
        "mma.sync.aligned.m16n8k16.row.col.f32.bf16.bf16.f32 " \
        "{%0,%1,%2,%3}, {%4,%5,%6,%7}, {%8,%9}, {%0,%1,%2,%3};" \
        : "+f"((c)[0]), "+f"((c)[1]), "+f"((c)[2]), "+f"((c)[3]) \
        : "r"((a)[0]), "r"((a)[1]), "r"((a)[2]), "r"((a)[3]), \
          "r"((b)[0]), "r"((b)[1]))

#define PACK_BF16X2(d, hi_f, lo_f) \
    asm("cvt.rn.bf16x2.f32 %0, %1, %2;" : "=r"(d) : "f"(hi_f), "f"(lo_f))

// ---------------------------------------------------------------------------
// Scratch (allocation-free rule: __device__ globals)
// ---------------------------------------------------------------------------
__device__ float g_q[(size_t)BT * DMODEL];
__device__ float g_k[(size_t)BT * DMODEL];
__device__ float2 g_rope_tab[SEQ * 64];

__device__ __nv_bfloat16 g_xhi[(size_t)BT * DMODEL];
__device__ __nv_bfloat16 g_xlo[(size_t)BT * DMODEL];
__device__ __nv_bfloat16 g_ohi[(size_t)BT * DMODEL];
__device__ __nv_bfloat16 g_olo[(size_t)BT * DMODEL];
__device__ __nv_bfloat16 g_wqhi[(size_t)DMODEL * DMODEL];
__device__ __nv_bfloat16 g_wqlo[(size_t)DMODEL * DMODEL];
__device__ __nv_bfloat16 g_wkhi[(size_t)DMODEL * DMODEL];
__device__ __nv_bfloat16 g_wklo[(size_t)DMODEL * DMODEL];
__device__ __nv_bfloat16 g_wvhi[(size_t)DMODEL * DMODEL];
__device__ __nv_bfloat16 g_wvlo[(size_t)DMODEL * DMODEL];
__device__ __nv_bfloat16 g_wohi[(size_t)DMODEL * DMODEL];
__device__ __nv_bfloat16 g_wolo[(size_t)DMODEL * DMODEL];

__device__ __nv_bfloat16 g_qhi[(size_t)BT * DMODEL];
__device__ __nv_bfloat16 g_qlo[(size_t)BT * DMODEL];
__device__ __nv_bfloat16 g_khi[(size_t)BT * DMODEL];
__device__ __nv_bfloat16 g_klo[(size_t)BT * DMODEL];
__device__ __nv_bfloat16 g_vhi[(size_t)BT * DMODEL];
__device__ __nv_bfloat16 g_vlo[(size_t)BT * DMODEL];

// ---------------------------------------------------------------------------
// Vectorized fp32 -> (bf16 hi, bf16 lo) split: 8 elems/thread
// ---------------------------------------------------------------------------
__device__ __forceinline__
void split8(const float* __restrict__ src,
            __nv_bfloat16* __restrict__ hi, __nv_bfloat16* __restrict__ lo,
            size_t i8) {
    float4 a = *(const float4*)(src + i8);
    float4 b = *(const float4*)(src + i8 + 4);
    float v[8] = {a.x, a.y, a.z, a.w, b.x, b.y, b.z, b.w};
    __nv_bfloat162 ph[4], pl[4];
#pragma unroll
    for (int j = 0; j < 4; j++) {
        __nv_bfloat16 h0 = __float2bfloat16(v[2*j]);
        __nv_bfloat16 h1 = __float2bfloat16(v[2*j+1]);
        ph[j].x = h0; ph[j].y = h1;
        pl[j].x = __float2bfloat16(v[2*j]   - __bfloat162float(h0));
        pl[j].y = __float2bfloat16(v[2*j+1] - __bfloat162float(h1));
    }
    *(uint4*)(hi + i8) = *(uint4*)ph;
    *(uint4*)(lo + i8) = *(uint4*)pl;
}

__global__ __launch_bounds__(256)
void split_bf16_v8(const float* __restrict__ src,
                   __nv_bfloat16* __restrict__ hi, __nv_bfloat16* __restrict__ lo,
                   size_t n) {
    size_t i8 = ((size_t)blockIdx.x * 256 + threadIdx.x) * 8;
    if (i8 >= n) return;
    split8(src, hi, lo, i8);
}

// Fused weight splits: blockIdx.y selects which weight (0=q,1=k,2=v,3=o).
__global__ __launch_bounds__(256)
void split_weights(const float* __restrict__ wq, const float* __restrict__ wk,
                   const float* __restrict__ wv, const float* __restrict__ wo) {
    const size_t nw = (size_t)DMODEL * DMODEL;
    size_t i8 = ((size_t)blockIdx.x * 256 + threadIdx.x) * 8;
    if (i8 >= nw) return;
    switch (blockIdx.y) {
        case 0: split8(wq, g_wqhi, g_wqlo, i8); break;
        case 1: split8(wk, g_wkhi, g_wklo, i8); break;
        case 2: split8(wv, g_wvhi, g_wvlo, i8); break;
        default: split8(wo, g_wohi, g_wolo, i8); break;
    }
}

// ---------------------------------------------------------------------------
// RoPE table in double precision (immune to --use_fast_math)
// ---------------------------------------------------------------------------
__global__ __launch_bounds__(256)
void rope_table_kernel() {
    int idx = blockIdx.x * blockDim.x + threadIdx.x;
    if (idx >= SEQ * 64) return;
    int i = idx & 63;
    int t = idx >> 6;
    float inv_freq = (float)exp(-log(10000.0) * ((double)i / 64.0));
    float ang_f = (float)t * inv_freq;
    double ang = (double)ang_f;
    g_rope_tab[idx] = make_float2((float)cos(ang), (float)sin(ang));
}

// ---------------------------------------------------------------------------
// RoPE + bf16 hi/lo split for q and k (fused)
// ---------------------------------------------------------------------------
__global__ __launch_bounds__(256)
void rope_split_kernel() {
    const size_t total = (size_t)BT * NHEAD * (HDIM / 2);
    size_t idx = (size_t)blockIdx.x * blockDim.x + threadIdx.x;
    if (idx >= total) return;

    int i  = (int)(idx & 63);
    int h  = (int)((idx >> 6) & (NHEAD - 1));
    int bt = (int)(idx >> 10);
    int t  = bt & (SEQ - 1);

    float2 cs = g_rope_tab[t * 64 + i];
    float c = cs.x, s = cs.y;

    size_t base = (size_t)bt * DMODEL + h * HDIM + i;

    float q1 = g_q[base], q2 = g_q[base + 64];
    float qa = q1 * c - q2 * s;
    float qb = q2 * c + q1 * s;
    __nv_bfloat16 qah = __float2bfloat16(qa);
    __nv_bfloat16 qbh = __float2bfloat16(qb);
    g_qhi[base]      = qah; g_qlo[base]      = __float2bfloat16(qa - __bfloat162float(qah));
    g_qhi[base + 64] = qbh; g_qlo[base + 64] = __float2bfloat16(qb - __bfloat162float(qbh));

    float k1 = g_k[base], k2 = g_k[base + 64];
    float ka = k1 * c - k2 * s;
    float kb = k2 * c + k1 * s;
    __nv_bfloat16 kah = __float2bfloat16(ka);
    __nv_bfloat16 kbh = __float2bfloat16(kb);
    g_khi[base]      = kah; g_klo[base]      = __float2bfloat16(ka - __bfloat162float(kah));
    g_khi[base + 64] = kbh; g_klo[base + 64] = __float2bfloat16(kb - __bfloat162float(kbh));
}

// ---------------------------------------------------------------------------
// bf16-split GEMM — unchanged from R16 (validated 67% tensor, 2 CTAs/SM).
// ---------------------------------------------------------------------------
#define BM 128
#define BN 128
#define BK 32
#define ROWB 80
#define TILE_B (128 * ROWB)
#define STAGE_B (4 * TILE_B)          // 40960 B
#define GEMM_SMEM (2 * STAGE_B)       // 81920 B
#define GTHREADS 128

__device__ __forceinline__
void gemm_body(const __nv_bfloat16* __restrict__ Ahi,
               const __nv_bfloat16* __restrict__ Alo,
               const __nv_bfloat16* __restrict__ Bhi,
               const __nv_bfloat16* __restrict__ Blo,
               float* __restrict__ Cf,
               __nv_bfloat16* __restrict__ Chi,
               __nv_bfloat16* __restrict__ Clo,
               int N, int K, char* smem) {
    const uint32_t sb = smem_to_u32(smem);
    const int tid  = threadIdx.x;
    const int lane = tid & 31;
    const int wid  = tid >> 5;
    const int warp_m = wid & 1;
    const int warp_n = wid >> 1;

    const int row0 = blockIdx.y * BM;
    const int col0 = blockIdx.x * BN;

    float acc[4][8][4];
#pragma unroll
    for (int mi = 0; mi < 4; mi++)
#pragma unroll
        for (int ni = 0; ni < 8; ni++)
#pragma unroll
            for (int e = 0; e < 4; e++) acc[mi][ni][e] = 0.f;

    const int r_ld  = tid >> 2;
    const int c_ld  = (tid & 3) * 16;
    const int ke_ld = (tid & 3) * 8;

    {
#pragma unroll
        for (int rnd = 0; rnd < 4; rnd++) {
            int r = r_ld + rnd * 32;
            uint32_t d = sb + r * ROWB + c_ld;
            size_t ga = (size_t)(row0 + r) * K + ke_ld;
            size_t gb = (size_t)(col0 + r) * K + ke_ld;
            CP_ASYNC_16(d + 0 * TILE_B, Ahi + ga);
            CP_ASYNC_16(d + 1 * TILE_B, Alo + ga);
            CP_ASYNC_16(d + 2 * TILE_B, Bhi + gb);
            CP_ASYNC_16(d + 3 * TILE_B, Blo + gb);
        }
        CP_ASYNC_COMMIT();
    }

    const int niter = K / BK;
    for (int kt = 0; kt < niter; kt++) {
        __syncthreads();

        if (kt + 1 < niter) {
            const int k0 = (kt + 1) * BK;
            const uint32_t base = sb + ((kt + 1) & 1) * STAGE_B;
#pragma unroll
            for (int rnd = 0; rnd < 4; rnd++) {
                int r = r_ld + rnd * 32;
                uint32_t d = base + r * ROWB + c_ld;
                size_t ga = (size_t)(row0 + r) * K + k0 + ke_ld;
                size_t gb = (size_t)(col0 + r) * K + k0 + ke_ld;
                CP_ASYNC_16(d + 0 * TILE_B, Ahi + ga);
                CP_ASYNC_16(d + 1 * TILE_B, Alo + ga);
                CP_ASYNC_16(d + 2 * TILE_B, Bhi + gb);
                CP_ASYNC_16(d + 3 * TILE_B, Blo + gb);
            }
        }
        CP_ASYNC_COMMIT();
        CP_ASYNC_WAIT_1();
        __syncthreads();

        const uint32_t base  = sb + (kt & 1) * STAGE_B;
        const uint32_t a_hiB = base + 0 * TILE_B;
        const uint32_t a_loB = base + 1 * TILE_B;
        const uint32_t b_hiB = base + 2 * TILE_B;
        const uint32_t b_loB = base + 3 * TILE_B;

#pragma unroll
        for (int ks = 0; ks < 2; ks++) {
            const int kb = ks * 32;

            uint32_t ah[4][4], al[4][4], bh[8][2], bl[8][2];
            const int ar = warp_m * 64 + (lane & 15);
            const uint32_t acol = kb + ((lane >> 4) << 4);
#pragma unroll
            for (int mi = 0; mi < 4; mi++) {
                uint32_t off = (uint32_t)(ar + mi * 16) * ROWB + acol;
                LDMATRIX_X4(ah[mi][0], ah[mi][1], ah[mi][2], ah[mi][3], a_hiB + off);
                LDMATRIX_X4(al[mi][0], al[mi][1], al[mi][2], al[mi][3], a_loB + off);
            }
            const int brr = warp_n * 64 + ((lane >> 4) & 1) * 8 + (lane & 7);
            const uint32_t bcol = kb + ((lane >> 3) & 1) * 16;
#pragma unroll
            for (int nb = 0; nb < 4; nb++) {
                uint32_t off = (uint32_t)(brr + nb * 16) * ROWB + bcol;
                LDMATRIX_X4(bh[2*nb][0], bh[2*nb][1], bh[2*nb+1][0], bh[2*nb+1][1],
                            b_hiB + off);
                LDMATRIX_X4(bl[2*nb][0], bl[2*nb][1], bl[2*nb+1][0], bl[2*nb+1][1],
                            b_loB + off);
            }
#pragma unroll
            for (int mi = 0; mi < 4; mi++)
#pragma unroll
                for (int ni = 0; ni < 8; ni++) {
                    MMA_BF16(acc[mi][ni], ah[mi], bh[ni]);
                    MMA_BF16(acc[mi][ni], ah[mi], bl[ni]);
                    MMA_BF16(acc[mi][ni], al[mi], bh[ni]);
                }
        }
    }

#pragma unroll
    for (int mi = 0; mi < 4; mi++) {
        int r = row0 + warp_m * 64 + mi * 16 + (lane >> 2);
#pragma unroll
        for (int ni = 0; ni < 8; ni++) {
            int c = col0 + warp_n * 64 + ni * 8 + (lane & 3) * 2;
            if (Cf) {
                *(float2*)(Cf + (size_t)r * N + c) =
                    make_float2(acc[mi][ni][0], acc[mi][ni][1]);
                *(float2*)(Cf + (size_t)(r + 8) * N + c) =
                    make_float2(acc[mi][ni][2], acc[mi][ni][3]);
            } else {
#pragma unroll
                for (int rr = 0; rr < 2; rr++) {
                    float v0 = acc[mi][ni][rr*2], v1 = acc[mi][ni][rr*2+1];
                    __nv_bfloat162 ph, pl;
                    ph.x = __float2bfloat16(v0);
                    ph.y = __float2bfloat16(v1);
                    pl.x = __float2bfloat16(v0 - __bfloat162float(ph.x));
                    pl.y = __float2bfloat16(v1 - __bfloat162float(ph.y));
                    size_t off = (size_t)(r + rr * 8) * N + c;
                    *(__nv_bfloat162*)(Chi + off) = ph;
                    *(__nv_bfloat162*)(Clo + off) = pl;
                }
            }
        }
    }
}

__global__ __launch_bounds__(GTHREADS, 2)
void gemm_qkv() {
    extern __shared__ char smem[];
    const int z = blockIdx.z;
    if (z == 0)
        gemm_body(g_xhi, g_xlo, g_wqhi, g_wqlo, g_q, nullptr, nullptr,
                  DMODEL, DMODEL, smem);
    else if (z == 1)
        gemm_body(g_xhi, g_xlo, g_wkhi, g_wklo, g_k, nullptr, nullptr,
                  DMODEL, DMODEL, smem);
    else
        gemm_body(g_xhi, g_xlo, g_wvhi, g_wvlo, nullptr, g_vhi, g_vlo,
                  DMODEL, DMODEL, smem);
}

__global__ __launch_bounds__(GTHREADS, 2)
void gemm_out(float* __restrict__ out) {
    extern __shared__ char smem[];
    gemm_body(g_ohi, g_olo, g_wohi, g_wolo, out, nullptr, nullptr,
              DMODEL, DMODEL, smem);
}

// ---------------------------------------------------------------------------
// Tensor-core flash attention — R17: K/V loads software-pipelined through the
// single K and V buffers (no extra smem).  Per iter:
//   wait(1)+sync  -> K(jb),Q resident  [V(jb) in flight]
//   S=QK^T, softmax
//   sync          -> K smem free; issue K(jb+1)+commit; pack P
//   wait(1)+sync  -> V(jb) resident    [K(jb+1) in flight]
//   P*V
//   sync          -> V smem free; issue V(jb+1)+commit
// Unconditional commits keep wait_group arithmetic uniform (empty at tail).
// ---------------------------------------------------------------------------
#define FROWB 272
#define FTILE (64 * FROWB)
#define SQH 0
#define SQL (1 * FTILE)
#define SKH (2 * FTILE)
#define SKL (3 * FTILE)
#define SVH (4 * FTILE)
#define SVL (5 * FTILE)
#define FA_SMEM (6 * FTILE)      // 104448 B

__global__ __launch_bounds__(128, 2)
void flash_attn_tc() {
    extern __shared__ char sm[];
    const uint32_t sb = smem_to_u32(sm);
    const int tid  = threadIdx.x;
    const int lane = tid & 31;
    const int warp = tid >> 5;

    const int mb = (int)gridDim.x - 1 - (int)blockIdx.x;
    const int bh = blockIdx.y;
    const int b  = bh >> 4;
    const int h  = bh & 15;
    const float scale = 0.08838834764831845f;

    const size_t hbase = (size_t)b * SEQ * DMODEL + (size_t)h * HDIM;

    // ---- prologue: Q, K(0), V(0) as three separate groups ----
    {
        const size_t q0 = hbase + (size_t)mb * 64 * DMODEL;
        for (int i = tid; i < 1024; i += 128) {
            int r = i >> 4, c = i & 15;
            uint32_t d = sb + r * FROWB + c * 16;
            size_t g = q0 + (size_t)r * DMODEL + c * 8;
            CP_ASYNC_16(d + SQH, g_qhi + g);
            CP_ASYNC_16(d + SQL, g_qlo + g);
        }
        CP_ASYNC_COMMIT();                       // group: Q
        for (int i = tid; i < 1024; i += 128) {
            int r = i >> 4, c = i & 15;
            uint32_t d = sb + r * FROWB + c * 16;
            size_t g = (size_t)r * DMODEL + c * 8;   // jb = 0
            CP_ASYNC_16(d + SKH, g_khi + hbase + g);
            CP_ASYNC_16(d + SKL, g_klo + hbase + g);
        }
        CP_ASYNC_COMMIT();                       // group: K(0)
        for (int i = tid; i < 1024; i += 128) {
            int r = i >> 4, c = i & 15;
            uint32_t d = sb + r * FROWB + c * 16;
            size_t g = (size_t)r * DMODEL + c * 8;
            CP_ASYNC_16(d + SVH, g_vhi + hbase + g);
            CP_ASYNC_16(d + SVL, g_vlo + hbase + g);
        }
        CP_ASYNC_COMMIT();                       // group: V(0)
    }

    const int r0 = lane >> 2;
    float m0 = -INFINITY, m1 = -INFINITY, l0 = 0.f, l1 = 0.f;
    float oacc[16][4];
#pragma unroll
    for (int nb = 0; nb < 16; nb++)
#pragma unroll
        for (int e = 0; e < 4; e++) oacc[nb][e] = 0.f;

    for (int jb = 0; jb <= mb; jb++) {
        CP_ASYNC_WAIT_1();            // K(jb) + Q resident; V(jb) may be in flight
        __syncthreads();

        // ---- S = Q*K^T (hi/lo split, 3 passes) ----
        float sacc[8][4];
#pragma unroll
        for (int j = 0; j < 8; j++)
#pragma unroll
            for (int e = 0; e < 4; e++) sacc[j][e] = 0.f;

#pragma unroll
        for (int ks = 0; ks < 8; ks++) {
            const int kb = ks * 32;
            uint32_t aqh[4], aql[4];
            uint32_t aaddr = sb + (uint32_t)(warp * 16 + (lane & 15)) * FROWB
                           + kb + ((lane >> 4) << 4);
            LDMATRIX_X4(aqh[0], aqh[1], aqh[2], aqh[3], aaddr + SQH);
            LDMATRIX_X4(aql[0], aql[1], aql[2], aql[3], aaddr + SQL);
#pragma unroll
            for (int nsl = 0; nsl < 4; nsl++) {
                uint32_t bkh[2][2], bkl[2][2];
                uint32_t baddr = sb
                    + (uint32_t)(nsl * 16 + ((lane >> 4) & 1) * 8 + (lane & 7)) * FROWB
                    + kb + ((lane >> 3) & 1) * 16;
                LDMATRIX_X4(bkh[0][0], bkh[0][1], bkh[1][0], bkh[1][1], baddr + SKH);
                LDMATRIX_X4(bkl[0][0], bkl[0][1], bkl[1][0], bkl[1][1], baddr + SKL);
#pragma unroll
                for (int t = 0; t < 2; t++) {
                    int j = nsl * 2 + t;
                    MMA_BF16(sacc[j], aqh, bkh[t]);
                    MMA_BF16(sacc[j], aqh, bkl[t]);
                    MMA_BF16(sacc[j], aql, bkh[t]);
                }
            }
        }

#pragma unroll
        for (int j = 0; j < 8; j++)
#pragma unroll
            for (int e = 0; e < 4; e++) sacc[j][e] *= scale;

        if (jb == mb) {
            const int row0 = warp * 16 + r0;
            const int row1 = row0 + 8;
#pragma unroll
            for (int j = 0; j < 8; j++) {
                int c0 = j * 8 + (lane & 3) * 2;
                if (c0     > row0) sacc[j][0] = -INFINITY;
                if (c0 + 1 > row0) sacc[j][1] = -INFINITY;
                if (c0     > row1) sacc[j][2] = -INFINITY;
                if (c0 + 1 > row1) sacc[j][3] = -INFINITY;
            }
        }

        // ---- online softmax (registers only) ----
        float mn0 = -INFINITY, mn1 = -INFINITY;
#pragma unroll
        for (int j = 0; j < 8; j++) {
            mn0 = fmaxf(mn0, fmaxf(sacc[j][0], sacc[j][1]));
            mn1 = fmaxf(mn1, fmaxf(sacc[j][2], sacc[j][3]));
        }
        mn0 = fmaxf(mn0, __shfl_xor_sync(0xffffffffu, mn0, 1));
        mn0 = fmaxf(mn0, __shfl_xor_sync(0xffffffffu, mn0, 2));
        mn1 = fmaxf(mn1, __shfl_xor_sync(0xffffffffu, mn1, 1));
        mn1 = fmaxf(mn1, __shfl_xor_sync(0xffffffffu, mn1, 2));
        mn0 = fmaxf(mn0, m0);
        mn1 = fmaxf(mn1, m1);

        float alpha0 = __expf(m0 - mn0);
        float alpha1 = __expf(m1 - mn1);
        m0 = mn0; m1 = mn1;
        l0 *= alpha0; l1 *= alpha1;
#pragma unroll
        for (int nb = 0; nb < 16; nb++) {
            oacc[nb][0] *= alpha0; oacc[nb][1] *= alpha0;
            oacc[nb][2] *= alpha1; oacc[nb][3] *= alpha1;
        }

        float rs0 = 0.f, rs1 = 0.f;
#pragma unroll
        for (int j = 0; j < 8; j++) {
            float p0 = __expf(sacc[j][0] - mn0);
            float p1 = __expf(sacc[j][1] - mn0);
            float p2 = __expf(sacc[j][2] - mn1);
            float p3 = __expf(sacc[j][3] - mn1);
            sacc[j][0] = p0; sacc[j][1] = p1; sacc[j][2] = p2; sacc[j][3] = p3;
            rs0 += p0 + p1; rs1 += p2 + p3;
        }
        rs0 += __shfl_xor_sync(0xffffffffu, rs0, 1);
        rs0 += __shfl_xor_sync(0xffffffffu, rs0, 2);
        rs1 += __shfl_xor_sync(0xffffffffu, rs1, 1);
        rs1 += __shfl_xor_sync(0xffffffffu, rs1, 2);
        l0 += rs0; l1 += rs1;

        __syncthreads();              // all warps done reading K smem
        // ---- prefetch K(jb+1) into K smem (overlaps P-pack + P*V) ----
        if (jb < mb) {
            const size_t k0 = hbase + (size_t)(jb + 1) * 64 * DMODEL;
            for (int i = tid; i < 1024; i += 128) {
                int r = i >> 4, c = i & 15;
                uint32_t d = sb + r * FROWB + c * 16;
                size_t g = k0 + (size_t)r * DMODEL + c * 8;
                CP_ASYNC_16(d + SKH, g_khi + g);
                CP_ASYNC_16(d + SKL, g_klo + g);
            }
        }
        CP_ASYNC_COMMIT();            // group: K(jb+1) (possibly empty)

        // ---- P fragments (hi/lo) from S accumulators (registers only) ----
        uint32_t aph[4][4], apl[4][4];
#pragma unroll
        for (int kb2 = 0; kb2 < 4; kb2++) {
            int j = kb2 * 2;
#pragma unroll
            for (int q = 0; q < 4; q++) {
                int jj = j + (q >> 1);
                int e0 = (q & 1) * 2;
                float p0 = sacc[jj][e0], p1 = sacc[jj][e0 + 1];
                float h0 = __bfloat162float(__float2bfloat16(p0));
                float h1 = __bfloat162float(__float2bfloat16(p1));
                PACK_BF16X2(aph[kb2][q], h1, h0);
                PACK_BF16X2(apl[kb2][q], p1 - h1, p0 - h0);
            }
        }

        CP_ASYNC_WAIT_1();            // V(jb) resident; K(jb+1) may be in flight
        __syncthreads();

        // ---- O += P*V (hi/lo split, 3 passes), V via ldmatrix.trans ----
#pragma unroll
        for (int kb2 = 0; kb2 < 4; kb2++) {
#pragma unroll
            for (int ns2 = 0; ns2 < 8; ns2++) {
                uint32_t bvh[2][2], bvl[2][2];
                uint32_t vaddr = sb
                    + (uint32_t)(kb2 * 16 + (lane & 7) + ((lane >> 3) & 1) * 8) * FROWB
                    + ns2 * 32 + ((lane >> 4) & 1) * 16;
                LDMATRIX_X4_TRANS(bvh[0][0], bvh[0][1], bvh[1][0], bvh[1][1], vaddr + SVH);
                LDMATRIX_X4_TRANS(bvl[0][0], bvl[0][1], bvl[1][0], bvl[1][1], vaddr + SVL);
#pragma unroll
                for (int t = 0; t < 2; t++) {
                    int nb = ns2 * 2 + t;
                    MMA_BF16(oacc[nb], aph[kb2], bvh[t]);
                    MMA_BF16(oacc[nb], apl[kb2], bvh[t]);
                    MMA_BF16(oacc[nb], aph[kb2], bvl[t]);
                }
            }
        }

        __syncthreads();              // all warps done reading V smem
        // ---- prefetch V(jb+1) into V smem (overlaps next S + softmax) ----
        if (jb < mb) {
            const size_t v0 = hbase + (size_t)(jb + 1) * 64 * DMODEL;
            for (int i = tid; i < 1024; i += 128) {
                int r = i >> 4, c = i & 15;
                uint32_t d = sb + r * FROWB + c * 16;
                size_t g = v0 + (size_t)r * DMODEL + c * 8;
                CP_ASYNC_16(d + SVH, g_vhi + g);
                CP_ASYNC_16(d + SVL, g_vlo + g);
            }
        }
        CP_ASYNC_COMMIT();            // group: V(jb+1) (possibly empty)
    }

    const float inv0 = 1.0f / l0;
    const float inv1 = 1.0f / l1;
    const size_t obase = hbase + (size_t)(mb * 64 + warp * 16) * DMODEL;
#pragma unroll
    for (int nb = 0; nb < 16; nb++) {
        int c = nb * 8 + (lane & 3) * 2;
#pragma unroll
        for (int rr = 0; rr < 2; rr++) {
            float v0 = oacc[nb][rr*2]     * (rr ? inv1 : inv0);
            float v1 = oacc[nb][rr*2 + 1] * (rr ? inv1 : inv0);
            __nv_bfloat162 ph, pl;
            ph.x = __float2bfloat16(v0);
            ph.y = __float2bfloat16(v1);
            pl.x = __float2bfloat16(v0 - __bfloat162float(ph.x));
            pl.y = __float2bfloat16(v1 - __bfloat162float(ph.y));
            size_t off = obase + (size_t)(r0 + rr * 8) * DMODEL + c;
            *(__nv_bfloat162*)(g_ohi + off) = ph;
            *(__nv_bfloat162*)(g_olo + off) = pl;
        }
    }
}

// ---------------------------------------------------------------------------
// Launch. Order: 1 x-split, 2 w-split, 3 rope_table, 4 gemm_qkv,
//                5 rope_split, 6 flash (ncu target), 7 gemm_out.
// ---------------------------------------------------------------------------
extern "C" void kernel_launch(void* const* d_in, const int* in_sizes, int n_in,
                              void* d_out, int out_size) {
    const float* x  = (const float*)d_in[0];
    const float* wq = (const float*)d_in[1];
    const float* wk = (const float*)d_in[2];
    const float* wv = (const float*)d_in[3];
    const float* wo = (const float*)d_in[4];
    float* out = (float*)d_out;

    __nv_bfloat16 *xhi, *xlo;
    cudaGetSymbolAddress((void**)&xhi, g_xhi);
    cudaGetSymbolAddress((void**)&xlo, g_xlo);

    const size_t nx = (size_t)BT * DMODEL;        // 16.7M
    const size_t nw = (size_t)DMODEL * DMODEL;    // 4.19M

    split_bf16_v8<<<(int)(nx / 2048), 256>>>(x, xhi, xlo, nx);
    split_weights<<<dim3((unsigned)(nw / 2048), 4), 256>>>(wq, wk, wv, wo);

    rope_table_kernel<<<(SEQ * 64 + 255) / 256, 256>>>();

    cudaFuncSetAttribute(gemm_qkv,
                         cudaFuncAttributeMaxDynamicSharedMemorySize, GEMM_SMEM);
    gemm_qkv<<<dim3(DMODEL / BN, BT / BM, 3), GTHREADS, GEMM_SMEM>>>();

    {
        size_t total = (size_t)BT * NHEAD * (HDIM / 2);
        rope_split_kernel<<<(int)((total + 255) / 256), 256>>>();
    }

    cudaFuncSetAttribute(flash_attn_tc,
                         cudaFuncAttributeMaxDynamicSharedMemorySize, FA_SMEM);
    flash_attn_tc<<<dim3(SEQ / 64, BATCH * NHEAD), 128, FA_SMEM>>>();

    cudaFuncSetAttribute(gemm_out,
                         cudaFuncAttributeMaxDynamicSharedMemorySize, GEMM_SMEM);
    gemm_out<<<dim3(DMODEL / BN, BT / BM, 1), GTHREADS, GEMM_SMEM>>>(out);
}